// round 1
// baseline (speedup 1.0000x reference)
#include <cuda_runtime.h>
#include <math.h>

// Problem constants
#define SLEN 1024
#define BSZ  32
#define IND  512
#define NH   8
#define HD   64
#define ROWS (SLEN*BSZ)          // 32768
#define NSLOW (NH*(3*HD+1))      // 1544
#define PAIRS (BSZ*NH)           // 256

// ---------------------------------------------------------------------------
// Scratch (static device globals; allocation inside kernel_launch is banned)
// ---------------------------------------------------------------------------
__device__ float g_h[(size_t)ROWS * IND];           // 64 MB  LN output
__device__ float g_qkvb[(size_t)ROWS * NSLOW];      // 202 MB GEMM1 output (raw)
__device__ float g_q[(size_t)PAIRS * SLEN * HD];    // 64 MB  normalized q, [p][t][d]
__device__ float g_k[(size_t)PAIRS * SLEN * HD];    // 64 MB
__device__ float g_v[(size_t)PAIRS * SLEN * HD];    // 64 MB
__device__ float g_beta[(size_t)PAIRS * SLEN];      // 1 MB
__device__ float g_o[(size_t)ROWS * IND];           // 64 MB  scan output, row=(t*32+b), col=h*64+d

// ---------------------------------------------------------------------------
// 1) LayerNorm: one warp per row of 512
// ---------------------------------------------------------------------------
__global__ __launch_bounds__(256) void ln_kernel(const float* __restrict__ x,
                                                 const float* __restrict__ gam,
                                                 const float* __restrict__ bet,
                                                 float* __restrict__ out)
{
    int warp = threadIdx.x >> 5, lane = threadIdx.x & 31;
    int r = blockIdx.x * 8 + warp;
    const float* xr = x + (size_t)r * IND;
    float v[16], s = 0.f, ss = 0.f;
#pragma unroll
    for (int u = 0; u < 16; u++) {
        float t = xr[u * 32 + lane];
        v[u] = t; s += t; ss += t * t;
    }
#pragma unroll
    for (int o = 16; o > 0; o >>= 1) {
        s  += __shfl_xor_sync(0xffffffffu, s,  o);
        ss += __shfl_xor_sync(0xffffffffu, ss, o);
    }
    float mu  = s * (1.f / IND);
    float var = ss * (1.f / IND) - mu * mu;
    float rs  = rsqrtf(var + 1e-5f);
    float* hr = out + (size_t)r * IND;
#pragma unroll
    for (int u = 0; u < 16; u++) {
        int c = u * 32 + lane;
        hr[c] = (v[u] - mu) * rs * gam[c] + bet[c];
    }
}

// ---------------------------------------------------------------------------
// 2/5) Tiled fp32 SGEMM, 128x128x8, 8x8 per thread, reg-prefetch double buffer.
//      C = A[M,K] @ B[K,N]  (+ X residual if RESID)
// ---------------------------------------------------------------------------
template<bool RESID>
__global__ __launch_bounds__(256) void sgemm128(const float* __restrict__ A,
                                                const float* __restrict__ B,
                                                const float* __restrict__ X,
                                                float* __restrict__ C,
                                                int M, int N, int K)
{
    const int BM = 128, BN = 128, BK = 8;
    __shared__ __align__(16) float As[BK][BM];
    __shared__ __align__(16) float Bs[BK][BN];

    int t  = threadIdx.x;
    int m0 = blockIdx.y * BM;
    int n0 = blockIdx.x * BN;
    int ar = t >> 1,  ak = (t & 1) * 4;     // A tile: 128 rows x 8 k
    int br = t >> 5,  bc = (t & 31) * 4;    // B tile: 8 k x 128 cols
    int ty = t >> 4,  tx = t & 15;

    const float* Aptr = A + (size_t)(m0 + ar) * K + ak;
    const float* Bptr = B + (size_t)br * N + n0 + bc;
    bool bvalid = (n0 + bc) < N;            // N is a multiple of 4 for both GEMMs

    float4 aReg = *(const float4*)Aptr;
    float4 bReg = bvalid ? *(const float4*)Bptr : make_float4(0.f, 0.f, 0.f, 0.f);

    float acc[8][8];
#pragma unroll
    for (int u = 0; u < 8; u++)
#pragma unroll
        for (int w = 0; w < 8; w++) acc[u][w] = 0.f;

    int ntiles = K / BK;
    for (int tile = 0; tile < ntiles; ++tile) {
        As[ak + 0][ar] = aReg.x; As[ak + 1][ar] = aReg.y;
        As[ak + 2][ar] = aReg.z; As[ak + 3][ar] = aReg.w;
        *(float4*)&Bs[br][bc] = bReg;
        __syncthreads();

        if (tile + 1 < ntiles) {
            aReg = *(const float4*)(Aptr + (size_t)(tile + 1) * BK);
            if (bvalid) bReg = *(const float4*)(Bptr + (size_t)(tile + 1) * BK * N);
        }

#pragma unroll
        for (int kk = 0; kk < BK; ++kk) {
            float ra[8], rb[8];
            *(float4*)&ra[0] = *(const float4*)&As[kk][ty * 8 + 0];
            *(float4*)&ra[4] = *(const float4*)&As[kk][ty * 8 + 4];
            *(float4*)&rb[0] = *(const float4*)&Bs[kk][tx * 8 + 0];
            *(float4*)&rb[4] = *(const float4*)&Bs[kk][tx * 8 + 4];
#pragma unroll
            for (int u = 0; u < 8; u++)
#pragma unroll
                for (int w = 0; w < 8; w++) acc[u][w] += ra[u] * rb[w];
        }
        __syncthreads();
    }

#pragma unroll
    for (int u = 0; u < 8; u++) {
        int m = m0 + ty * 8 + u;
#pragma unroll
        for (int w = 0; w < 8; w++) {
            int n = n0 + tx * 8 + w;
            if (n < N) {
                float val = acc[u][w];
                if (RESID) val += X[(size_t)m * N + n];
                C[(size_t)m * N + n] = val;
            }
        }
    }
}

// ---------------------------------------------------------------------------
// 3) Activation / repack: elu+1 + sum-norm on q,k; sigmoid on beta.
//    One block per row r=(s*32+b); one warp per head.
//    Output layout [p=b*8+h][t][d] for sequential streaming in the scan.
// ---------------------------------------------------------------------------
__global__ __launch_bounds__(256) void act_kernel(const float* __restrict__ qkvb,
                                                  float* __restrict__ qo,
                                                  float* __restrict__ ko,
                                                  float* __restrict__ vo,
                                                  float* __restrict__ bo)
{
    int r = blockIdx.x;
    int hh = threadIdx.x >> 5, lane = threadIdx.x & 31;
    int s = r >> 5, b = r & 31;
    int p = b * NH + hh;
    const float* base = qkvb + (size_t)r * NSLOW + hh * (3 * HD + 1);
    size_t dst = ((size_t)p * SLEN + s) * HD;

    // q
    float q0 = base[lane], q1 = base[lane + 32];
    q0 = (q0 > 0.f) ? q0 + 1.f : expf(q0);
    q1 = (q1 > 0.f) ? q1 + 1.f : expf(q1);
    float qs = q0 + q1;
#pragma unroll
    for (int o = 16; o > 0; o >>= 1) qs += __shfl_xor_sync(0xffffffffu, qs, o);
    float qi = 1.f / qs;
    qo[dst + lane] = q0 * qi; qo[dst + lane + 32] = q1 * qi;

    // k
    float k0 = base[64 + lane], k1 = base[64 + lane + 32];
    k0 = (k0 > 0.f) ? k0 + 1.f : expf(k0);
    k1 = (k1 > 0.f) ? k1 + 1.f : expf(k1);
    float ks = k0 + k1;
#pragma unroll
    for (int o = 16; o > 0; o >>= 1) ks += __shfl_xor_sync(0xffffffffu, ks, o);
    float ki = 1.f / ks;
    ko[dst + lane] = k0 * ki; ko[dst + lane + 32] = k1 * ki;

    // v (copy), beta (sigmoid)
    vo[dst + lane]      = base[128 + lane];
    vo[dst + lane + 32] = base[128 + lane + 32];
    if (lane == 0)
        bo[(size_t)p * SLEN + s] = 1.f / (1.f + expf(-base[192]));
}

// ---------------------------------------------------------------------------
// 4) Delta-rule scan. One block per (b,h) pair; 256 threads.
//    Thread (i = t>>2, jg = t&3) owns W[i][jg*16 : jg*16+16] in registers.
//    Per step: v_old = W k (partial dot + shfl-xor reduce over jg),
//              W += beta*(v-v_old) k^T, o = W q.
//    Global loads for step s+1 are register-prefetched under step s's compute;
//    smem double-buffered; one barrier per step.
// ---------------------------------------------------------------------------
__global__ __launch_bounds__(256) void recur_kernel(const float* __restrict__ q,
                                                    const float* __restrict__ k,
                                                    const float* __restrict__ v,
                                                    const float* __restrict__ bta,
                                                    float* __restrict__ o)
{
    int p = blockIdx.x;             // b*8 + h
    int t = threadIdx.x;
    int i = t >> 2, jg = t & 3;
    int b = p >> 3, hh = p & 7;

    const float* qp = q + (size_t)p * SLEN * HD;
    const float* kp = k + (size_t)p * SLEN * HD;
    const float* vp = v + (size_t)p * SLEN * HD;
    const float* bp = bta + (size_t)p * SLEN;
    float* op = o + (size_t)b * IND + hh * HD + i;

    float W[16];
#pragma unroll
    for (int u = 0; u < 16; u++) W[u] = 0.f;

    __shared__ __align__(16) float sk[2][HD];
    __shared__ __align__(16) float sq[2][HD];
    __shared__ __align__(16) float sv[2][HD];
    __shared__ float sb[2];

    // prologue: stage step 0
    {
        float reg = 0.f;
        if (t < 64)        reg = kp[t];
        else if (t < 128)  reg = qp[t - 64];
        else if (t < 192)  reg = vp[t - 128];
        else if (t == 192) reg = bp[0];
        if (t < 64)        sk[0][t] = reg;
        else if (t < 128)  sq[0][t - 64] = reg;
        else if (t < 192)  sv[0][t - 128] = reg;
        else if (t == 192) sb[0] = reg;
    }
    __syncthreads();

    for (int s = 0; s < SLEN; ++s) {
        int buf = s & 1;

        // prefetch next step's inputs (hidden under this step's compute)
        float nreg = 0.f;
        if (s + 1 < SLEN) {
            int off = (s + 1) * HD;
            if (t < 64)        nreg = kp[off + t];
            else if (t < 128)  nreg = qp[off + t - 64];
            else if (t < 192)  nreg = vp[off + t - 128];
            else if (t == 192) nreg = bp[s + 1];
        }

        float kv[16], qv[16];
#pragma unroll
        for (int u = 0; u < 4; u++) {
            *(float4*)&kv[4 * u] = *(const float4*)&sk[buf][jg * 16 + 4 * u];
            *(float4*)&qv[4 * u] = *(const float4*)&sq[buf][jg * 16 + 4 * u];
        }
        float vi = sv[buf][i];
        float bt = sb[buf];

        // v_old partial dot (4-way split accumulators to shorten the chain)
        float a0 = 0.f, a1 = 0.f, a2 = 0.f, a3 = 0.f;
#pragma unroll
        for (int u = 0; u < 4; u++) {
            a0 += W[u]      * kv[u];
            a1 += W[4 + u]  * kv[4 + u];
            a2 += W[8 + u]  * kv[8 + u];
            a3 += W[12 + u] * kv[12 + u];
        }
        float dk = (a0 + a1) + (a2 + a3);
        dk += __shfl_xor_sync(0xffffffffu, dk, 1);
        dk += __shfl_xor_sync(0xffffffffu, dk, 2);

        float upd = bt * (vi - dk);
#pragma unroll
        for (int u = 0; u < 16; u++) W[u] += upd * kv[u];

        // o = W q
        float c0 = 0.f, c1 = 0.f, c2 = 0.f, c3 = 0.f;
#pragma unroll
        for (int u = 0; u < 4; u++) {
            c0 += W[u]      * qv[u];
            c1 += W[4 + u]  * qv[4 + u];
            c2 += W[8 + u]  * qv[8 + u];
            c3 += W[12 + u] * qv[12 + u];
        }
        float dq = (c0 + c1) + (c2 + c3);
        dq += __shfl_xor_sync(0xffffffffu, dq, 1);
        dq += __shfl_xor_sync(0xffffffffu, dq, 2);
        if (jg == 0) op[(size_t)s * BSZ * IND] = dq;

        // stage next step into the other buffer
        int nbuf = buf ^ 1;
        if (t < 64)        sk[nbuf][t] = nreg;
        else if (t < 128)  sq[nbuf][t - 64] = nreg;
        else if (t < 192)  sv[nbuf][t - 128] = nreg;
        else if (t == 192) sb[nbuf] = nreg;
        __syncthreads();
    }
}

// ---------------------------------------------------------------------------
// launch
// ---------------------------------------------------------------------------
extern "C" void kernel_launch(void* const* d_in, const int* in_sizes, int n_in,
                              void* d_out, int out_size)
{
    const float* x   = (const float*)d_in[0];   // [1024,32,512]
    const float* gam = (const float*)d_in[1];   // [512]
    const float* bet = (const float*)d_in[2];   // [512]
    const float* ws  = (const float*)d_in[3];   // [512,1544]
    const float* wo  = (const float*)d_in[4];   // [512,512]
    float* out = (float*)d_out;

    float *p_h, *p_qkvb, *p_q, *p_k, *p_v, *p_b, *p_o;
    cudaGetSymbolAddress((void**)&p_h,    g_h);
    cudaGetSymbolAddress((void**)&p_qkvb, g_qkvb);
    cudaGetSymbolAddress((void**)&p_q,    g_q);
    cudaGetSymbolAddress((void**)&p_k,    g_k);
    cudaGetSymbolAddress((void**)&p_v,    g_v);
    cudaGetSymbolAddress((void**)&p_b,    g_beta);
    cudaGetSymbolAddress((void**)&p_o,    g_o);

    // 1) LayerNorm
    ln_kernel<<<ROWS / 8, 256>>>(x, gam, bet, p_h);

    // 2) GEMM1: h @ w_slow -> qkvb   (M=32768, N=1544, K=512)
    {
        dim3 grid((NSLOW + 127) / 128, ROWS / 128);
        sgemm128<false><<<grid, 256>>>(p_h, ws, nullptr, p_qkvb, ROWS, NSLOW, IND);
    }

    // 3) activations + repack
    act_kernel<<<ROWS, 256>>>(p_qkvb, p_q, p_k, p_v, p_b);

    // 4) delta-rule scan
    recur_kernel<<<PAIRS, 256>>>(p_q, p_k, p_v, p_b, p_o);

    // 5) GEMM2: o @ w_out + x -> out (M=32768, N=512, K=512)
    {
        dim3 grid(IND / 128, ROWS / 128);
        sgemm128<true><<<grid, 256>>>(p_o, wo, x, out, ROWS, IND, IND);
    }
}

// round 3
// speedup vs baseline: 2.0279x; 2.0279x over previous
#include <cuda_runtime.h>
#include <math.h>
#include <stdint.h>

// Problem constants
#define SLEN 1024
#define BSZ  32
#define IND  512
#define NH   8
#define HD   64
#define ROWS (SLEN*BSZ)          // 32768
#define NSLOW (NH*(3*HD+1))      // 1544
#define PAIRS (BSZ*NH)           // 256

// ---------------------------------------------------------------------------
// Scratch (static device globals; allocation inside kernel_launch is banned)
// ---------------------------------------------------------------------------
__device__ float g_h[(size_t)ROWS * IND];           // LN output
__device__ float g_qkvb[(size_t)ROWS * NSLOW];      // GEMM1 output
__device__ float g_q[(size_t)PAIRS * SLEN * HD];    // [p][t][d]
__device__ float g_k[(size_t)PAIRS * SLEN * HD];
__device__ float g_v[(size_t)PAIRS * SLEN * HD];
__device__ float g_beta[(size_t)PAIRS * SLEN];
__device__ float g_o[(size_t)ROWS * IND];           // row=(t*32+b), col=h*64+d

// ---------------------------------------------------------------------------
// 1) LayerNorm: one warp per row of 512
// ---------------------------------------------------------------------------
__global__ __launch_bounds__(256) void ln_kernel(const float* __restrict__ x,
                                                 const float* __restrict__ gam,
                                                 const float* __restrict__ bet,
                                                 float* __restrict__ out)
{
    int warp = threadIdx.x >> 5, lane = threadIdx.x & 31;
    int r = blockIdx.x * 8 + warp;
    const float* xr = x + (size_t)r * IND;
    float v[16], s = 0.f, ss = 0.f;
#pragma unroll
    for (int u = 0; u < 16; u++) {
        float t = xr[u * 32 + lane];
        v[u] = t; s += t; ss += t * t;
    }
#pragma unroll
    for (int o = 16; o > 0; o >>= 1) {
        s  += __shfl_xor_sync(0xffffffffu, s,  o);
        ss += __shfl_xor_sync(0xffffffffu, ss, o);
    }
    float mu  = s * (1.f / IND);
    float var = ss * (1.f / IND) - mu * mu;
    float rs  = rsqrtf(var + 1e-5f);
    float* hr = out + (size_t)r * IND;
#pragma unroll
    for (int u = 0; u < 16; u++) {
        int c = u * 32 + lane;
        hr[c] = (v[u] - mu) * rs * gam[c] + bet[c];
    }
}

// ---------------------------------------------------------------------------
// tf32 helpers
// ---------------------------------------------------------------------------
__device__ __forceinline__ uint32_t f2tf32(float x) {
    uint32_t r;
    asm("cvt.rna.tf32.f32 %0, %1;" : "=r"(r) : "f"(x));
    return r;
}

__device__ __forceinline__ void mma_tf32(float c[4],
                                         uint32_t a0, uint32_t a1, uint32_t a2, uint32_t a3,
                                         uint32_t b0, uint32_t b1)
{
    asm volatile(
        "mma.sync.aligned.m16n8k8.row.col.f32.tf32.tf32.f32 "
        "{%0,%1,%2,%3},{%4,%5,%6,%7},{%8,%9},{%0,%1,%2,%3};\n"
        : "+f"(c[0]), "+f"(c[1]), "+f"(c[2]), "+f"(c[3])
        : "r"(a0), "r"(a1), "r"(a2), "r"(a3), "r"(b0), "r"(b1));
}

// ---------------------------------------------------------------------------
// 2/5) tf32 tensor-core GEMM, 128x128x16 tiles, 256 threads (8 warps),
//      warp tile 64x32 via m16n8k8. C = A[M,K]@B[K,N] (+X if RESID).
//      A,B fp32 in global; converted to tf32 once at smem store.
// ---------------------------------------------------------------------------
template<bool RESID>
__global__ __launch_bounds__(256) void tgemm(const float* __restrict__ A,
                                             const float* __restrict__ B,
                                             const float* __restrict__ X,
                                             float* __restrict__ C,
                                             int M, int N, int K)
{
    __shared__ uint32_t As[2][128][20];   // row-major, pad 16->20 (conflict-free frags)
    __shared__ uint32_t Bs[2][16][132];   // row-major, pad 128->132

    int t = threadIdx.x;
    int m0 = blockIdx.y * 128, n0 = blockIdx.x * 128;
    int warp = t >> 5, lane = t & 31;
    int wm = warp >> 2, wn = warp & 3;     // 2 x 4 warp grid
    int g = lane >> 2, tg = lane & 3;

    // global-load mapping: two float4 per thread per tile for each of A and B
    int fa[2] = { t, t + 256 };
    int raA[2], caA[2], raB[2], caB[2];
    bool bval[2];
#pragma unroll
    for (int u = 0; u < 2; u++) {
        raA[u] = fa[u] >> 2;  caA[u] = (fa[u] & 3) * 4;       // A tile 128x16
        raB[u] = fa[u] >> 5;  caB[u] = (fa[u] & 31) * 4;      // B tile 16x128
        bval[u] = (n0 + caB[u]) < N;
    }

    float acc[4][4][4];
#pragma unroll
    for (int im = 0; im < 4; im++)
#pragma unroll
        for (int jn = 0; jn < 4; jn++)
#pragma unroll
            for (int u = 0; u < 4; u++) acc[im][jn][u] = 0.f;

    const int ntiles = K / 16;
    float4 aR[2], bR[2];

    // prologue: load tile 0
#pragma unroll
    for (int u = 0; u < 2; u++) {
        aR[u] = *(const float4*)(A + (size_t)(m0 + raA[u]) * K + caA[u]);
        bR[u] = bval[u] ? *(const float4*)(B + (size_t)raB[u] * N + n0 + caB[u])
                        : make_float4(0.f, 0.f, 0.f, 0.f);
    }
#pragma unroll
    for (int u = 0; u < 2; u++) {
        As[0][raA[u]][caA[u] + 0] = f2tf32(aR[u].x);
        As[0][raA[u]][caA[u] + 1] = f2tf32(aR[u].y);
        As[0][raA[u]][caA[u] + 2] = f2tf32(aR[u].z);
        As[0][raA[u]][caA[u] + 3] = f2tf32(aR[u].w);
        Bs[0][raB[u]][caB[u] + 0] = f2tf32(bR[u].x);
        Bs[0][raB[u]][caB[u] + 1] = f2tf32(bR[u].y);
        Bs[0][raB[u]][caB[u] + 2] = f2tf32(bR[u].z);
        Bs[0][raB[u]][caB[u] + 3] = f2tf32(bR[u].w);
    }
    __syncthreads();

    int buf = 0;
    for (int tile = 0; tile < ntiles; ++tile) {
        // prefetch next tile (global -> regs)
        if (tile + 1 < ntiles) {
#pragma unroll
            for (int u = 0; u < 2; u++) {
                aR[u] = *(const float4*)(A + (size_t)(m0 + raA[u]) * K + (tile + 1) * 16 + caA[u]);
                bR[u] = bval[u] ? *(const float4*)(B + (size_t)((tile + 1) * 16 + raB[u]) * N + n0 + caB[u])
                                : make_float4(0.f, 0.f, 0.f, 0.f);
            }
        }

        // compute: two k8 sub-steps
#pragma unroll
        for (int kk = 0; kk < 16; kk += 8) {
            uint32_t a[4][4], b[4][2];
#pragma unroll
            for (int im = 0; im < 4; im++) {
                int r0 = wm * 64 + im * 16;
                a[im][0] = As[buf][r0 + g][kk + tg];
                a[im][1] = As[buf][r0 + g + 8][kk + tg];
                a[im][2] = As[buf][r0 + g][kk + tg + 4];
                a[im][3] = As[buf][r0 + g + 8][kk + tg + 4];
            }
#pragma unroll
            for (int jn = 0; jn < 4; jn++) {
                int c0 = wn * 32 + jn * 8;
                b[jn][0] = Bs[buf][kk + tg][c0 + g];
                b[jn][1] = Bs[buf][kk + tg + 4][c0 + g];
            }
#pragma unroll
            for (int im = 0; im < 4; im++)
#pragma unroll
                for (int jn = 0; jn < 4; jn++)
                    mma_tf32(acc[im][jn], a[im][0], a[im][1], a[im][2], a[im][3],
                             b[jn][0], b[jn][1]);
        }

        // store next tile into other buffer
        if (tile + 1 < ntiles) {
            int nb = buf ^ 1;
#pragma unroll
            for (int u = 0; u < 2; u++) {
                As[nb][raA[u]][caA[u] + 0] = f2tf32(aR[u].x);
                As[nb][raA[u]][caA[u] + 1] = f2tf32(aR[u].y);
                As[nb][raA[u]][caA[u] + 2] = f2tf32(aR[u].z);
                As[nb][raA[u]][caA[u] + 3] = f2tf32(aR[u].w);
                Bs[nb][raB[u]][caB[u] + 0] = f2tf32(bR[u].x);
                Bs[nb][raB[u]][caB[u] + 1] = f2tf32(bR[u].y);
                Bs[nb][raB[u]][caB[u] + 2] = f2tf32(bR[u].z);
                Bs[nb][raB[u]][caB[u] + 3] = f2tf32(bR[u].w);
            }
        }
        __syncthreads();
        buf ^= 1;
    }

    // epilogue
#pragma unroll
    for (int im = 0; im < 4; im++) {
        int r0 = m0 + wm * 64 + im * 16 + g;
#pragma unroll
        for (int jn = 0; jn < 4; jn++) {
            int col = n0 + wn * 32 + jn * 8 + tg * 2;
            if (col < N) {
                size_t o0 = (size_t)r0 * N + col;
                size_t o1 = (size_t)(r0 + 8) * N + col;
                float v0 = acc[im][jn][0], v1 = acc[im][jn][1];
                float v2 = acc[im][jn][2], v3 = acc[im][jn][3];
                if (RESID) {
                    v0 += X[o0]; v1 += X[o0 + 1];
                    v2 += X[o1]; v3 += X[o1 + 1];
                }
                C[o0] = v0; C[o0 + 1] = v1;
                C[o1] = v2; C[o1 + 1] = v3;
            }
        }
    }
}

// ---------------------------------------------------------------------------
// 3) Activation / repack: elu+1 + sum-norm on q,k; sigmoid on beta.
// ---------------------------------------------------------------------------
__global__ __launch_bounds__(256) void act_kernel(const float* __restrict__ qkvb,
                                                  float* __restrict__ qo,
                                                  float* __restrict__ ko,
                                                  float* __restrict__ vo,
                                                  float* __restrict__ bo)
{
    int r = blockIdx.x;
    int hh = threadIdx.x >> 5, lane = threadIdx.x & 31;
    int s = r >> 5, b = r & 31;
    int p = b * NH + hh;
    const float* base = qkvb + (size_t)r * NSLOW + hh * (3 * HD + 1);
    size_t dst = ((size_t)p * SLEN + s) * HD;

    float q0 = base[lane], q1 = base[lane + 32];
    q0 = (q0 > 0.f) ? q0 + 1.f : expf(q0);
    q1 = (q1 > 0.f) ? q1 + 1.f : expf(q1);
    float qs = q0 + q1;
#pragma unroll
    for (int o = 16; o > 0; o >>= 1) qs += __shfl_xor_sync(0xffffffffu, qs, o);
    float qi = 1.f / qs;
    qo[dst + lane] = q0 * qi; qo[dst + lane + 32] = q1 * qi;

    float k0 = base[64 + lane], k1 = base[64 + lane + 32];
    k0 = (k0 > 0.f) ? k0 + 1.f : expf(k0);
    k1 = (k1 > 0.f) ? k1 + 1.f : expf(k1);
    float ks = k0 + k1;
#pragma unroll
    for (int o = 16; o > 0; o >>= 1) ks += __shfl_xor_sync(0xffffffffu, ks, o);
    float ki = 1.f / ks;
    ko[dst + lane] = k0 * ki; ko[dst + lane + 32] = k1 * ki;

    vo[dst + lane]      = base[128 + lane];
    vo[dst + lane + 32] = base[128 + lane + 32];
    if (lane == 0)
        bo[(size_t)p * SLEN + s] = 1.f / (1.f + expf(-base[192]));
}

// ---------------------------------------------------------------------------
// 4) Delta-rule scan, chunked staging (8 steps per smem round).
//    One block per (b,h); thread (i=t>>2, jg=t&3) owns W[i][jg*16:+16] in regs.
// ---------------------------------------------------------------------------
#define CH 8
#define NCH (SLEN / CH)

__global__ __launch_bounds__(256) void recur_kernel(const float* __restrict__ q,
                                                    const float* __restrict__ k,
                                                    const float* __restrict__ v,
                                                    const float* __restrict__ bta,
                                                    float* __restrict__ o)
{
    int p = blockIdx.x;             // b*8 + h
    int t = threadIdx.x;
    int i = t >> 2, jg = t & 3;
    int b = p >> 3, hh = p & 7;

    const float4* kp4 = (const float4*)(k + (size_t)p * SLEN * HD);
    const float4* qp4 = (const float4*)(q + (size_t)p * SLEN * HD);
    const float4* vp4 = (const float4*)(v + (size_t)p * SLEN * HD);
    const float4* bp4 = (const float4*)(bta + (size_t)p * SLEN);
    float* op = o + (size_t)b * IND + hh * HD + i;

    float W[16];
#pragma unroll
    for (int u = 0; u < 16; u++) W[u] = 0.f;

    __shared__ __align__(16) float sk[2][CH][HD];
    __shared__ __align__(16) float sq[2][CH][HD];
    __shared__ __align__(16) float sv[2][CH][HD];
    __shared__ __align__(16) float sb[2][CH];

    // per-thread staging slots: f in {t, t+256}
    // f<128 -> k float4 f; f<256 -> q f-128; f<384 -> v f-256; f==384/385 -> beta
    int f0 = t, f1 = t + 256;

    // prologue: chunk 0
    float4 r0, r1;
    {
        r0 = (f0 < 128) ? kp4[f0] : ((f0 < 256) ? qp4[f0 - 128] : vp4[f0 - 256]);
        if (f1 < 384)      r1 = vp4[f1 - 256];
        else if (f1 == 384) r1 = bp4[0];
        else               r1 = bp4[1];
        if (f0 < 128)      ((float4*)sk[0])[f0] = r0;
        else if (f0 < 256) ((float4*)sq[0])[f0 - 128] = r0;
        else               ((float4*)sv[0])[f0 - 256] = r0;
        if (f1 < 384)      ((float4*)sv[0])[f1 - 256] = r1;
        else if (f1 == 384)((float4*)sb[0])[0] = r1;
        else               ((float4*)sb[0])[1] = r1;
    }
    __syncthreads();

    for (int c = 0; c < NCH; ++c) {
        int rb = c & 1;

        // prefetch chunk c+1 into regs (hidden under this chunk's compute)
        if (c + 1 < NCH) {
            int base4 = (c + 1) * CH * (HD / 4);   // 128 float4 per array per chunk
            r0 = (f0 < 128) ? kp4[base4 + f0]
               : ((f0 < 256) ? qp4[base4 + f0 - 128] : vp4[base4 + f0 - 256]);
            if (f1 < 384)       r1 = vp4[base4 + f1 - 256];
            else if (f1 == 384) r1 = bp4[(c + 1) * 2];
            else                r1 = bp4[(c + 1) * 2 + 1];
        }

#pragma unroll
        for (int sl = 0; sl < CH; ++sl) {
            float kv[16], qv[16];
#pragma unroll
            for (int u = 0; u < 4; u++) {
                *(float4*)&kv[4 * u] = *(const float4*)&sk[rb][sl][jg * 16 + 4 * u];
                *(float4*)&qv[4 * u] = *(const float4*)&sq[rb][sl][jg * 16 + 4 * u];
            }
            float vi = sv[rb][sl][i];
            float bt = sb[rb][sl];

            float a0 = 0.f, a1 = 0.f, a2 = 0.f, a3 = 0.f;
#pragma unroll
            for (int u = 0; u < 4; u++) {
                a0 += W[u]      * kv[u];
                a1 += W[4 + u]  * kv[4 + u];
                a2 += W[8 + u]  * kv[8 + u];
                a3 += W[12 + u] * kv[12 + u];
            }
            float dk = (a0 + a1) + (a2 + a3);
            dk += __shfl_xor_sync(0xffffffffu, dk, 1);
            dk += __shfl_xor_sync(0xffffffffu, dk, 2);

            float upd = bt * (vi - dk);
#pragma unroll
            for (int u = 0; u < 16; u++) W[u] += upd * kv[u];

            float c0 = 0.f, c1 = 0.f, c2 = 0.f, c3 = 0.f;
#pragma unroll
            for (int u = 0; u < 4; u++) {
                c0 += W[u]      * qv[u];
                c1 += W[4 + u]  * qv[4 + u];
                c2 += W[8 + u]  * qv[8 + u];
                c3 += W[12 + u] * qv[12 + u];
            }
            float dq = (c0 + c1) + (c2 + c3);
            dq += __shfl_xor_sync(0xffffffffu, dq, 1);
            dq += __shfl_xor_sync(0xffffffffu, dq, 2);
            if (jg == 0) op[(size_t)(c * CH + sl) * BSZ * IND] = dq;
        }

        __syncthreads();   // everyone done reading buffer rb^1 (prev chunk)
        if (c + 1 < NCH) {
            int wb = rb ^ 1;
            if (f0 < 128)      ((float4*)sk[wb])[f0] = r0;
            else if (f0 < 256) ((float4*)sq[wb])[f0 - 128] = r0;
            else               ((float4*)sv[wb])[f0 - 256] = r0;
            if (f1 < 384)      ((float4*)sv[wb])[f1 - 256] = r1;
            else if (f1 == 384)((float4*)sb[wb])[0] = r1;
            else               ((float4*)sb[wb])[1] = r1;
        }
        __syncthreads();
    }
}

// ---------------------------------------------------------------------------
// launch
// ---------------------------------------------------------------------------
extern "C" void kernel_launch(void* const* d_in, const int* in_sizes, int n_in,
                              void* d_out, int out_size)
{
    const float* x   = (const float*)d_in[0];   // [1024,32,512]
    const float* gam = (const float*)d_in[1];   // [512]
    const float* bet = (const float*)d_in[2];   // [512]
    const float* ws  = (const float*)d_in[3];   // [512,1544]
    const float* wo  = (const float*)d_in[4];   // [512,512]
    float* out = (float*)d_out;

    float *p_h, *p_qkvb, *p_q, *p_k, *p_v, *p_b, *p_o;
    cudaGetSymbolAddress((void**)&p_h,    g_h);
    cudaGetSymbolAddress((void**)&p_qkvb, g_qkvb);
    cudaGetSymbolAddress((void**)&p_q,    g_q);
    cudaGetSymbolAddress((void**)&p_k,    g_k);
    cudaGetSymbolAddress((void**)&p_v,    g_v);
    cudaGetSymbolAddress((void**)&p_b,    g_beta);
    cudaGetSymbolAddress((void**)&p_o,    g_o);

    // 1) LayerNorm
    ln_kernel<<<ROWS / 8, 256>>>(x, gam, bet, p_h);

    // 2) GEMM1: h @ w_slow -> qkvb   (M=32768, N=1544, K=512)
    {
        dim3 grid((NSLOW + 127) / 128, ROWS / 128);
        tgemm<false><<<grid, 256>>>(p_h, ws, nullptr, p_qkvb, ROWS, NSLOW, IND);
    }

    // 3) activations + repack
    act_kernel<<<ROWS, 256>>>(p_qkvb, p_q, p_k, p_v, p_b);

    // 4) delta-rule scan
    recur_kernel<<<PAIRS, 256>>>(p_q, p_k, p_v, p_b, p_o);

    // 5) GEMM2: o @ w_out + x -> out (M=32768, N=512, K=512)
    {
        dim3 grid(IND / 128, ROWS / 128);
        tgemm<true><<<grid, 256>>>(p_o, wo, x, out, ROWS, IND, IND);
    }
}